// round 10
// baseline (speedup 1.0000x reference)
#include <cuda_runtime.h>
#include <cstdint>

#define BB 16
#define TT 64
#define F0D 8
#define NN 100
#define NEXD 15
#define LD 16            // NEX+1
#define F1C 32
#define F2C 64
#define BT (BB*TT)       // 1024
#define MTOT (BT*NN)     // 102400
#define PLANE (BT*F0D*NN) // 819200 floats per k-plane (layout [bt][n*8+f])

// Scratch (static __device__ — no allocation at runtime)
__device__ float Zbuf[16 * PLANE];          // [k][bt][n][f]  (plane 0 unused; k=0 comes from x)
__device__ float Q1buf[F1C * 6 * MTOT];     // [c*6+i][g]
__device__ float Q2buf[F2C * 2 * MTOT];     // [d*2+i][g]
__device__ float W1T[128 * 64];             // fc1 weights transposed: [r][u]

// packed f32x2 helpers (bitwise-identical to two scalar RN fmas)
#define FMA2(acc, a, b) asm("fma.rn.f32x2 %0, %1, %2, %0;" : "+l"(acc) : "l"(a), "l"(b))
__device__ __forceinline__ unsigned long long bcast2(float s) {
    unsigned long long r;
    asm("mov.b64 %0, {%1, %1};" : "=l"(r) : "r"(__float_as_uint(s)));
    return r;
}

// ---------------------------------------------------------------------------
// One-time fc1 weight transpose: W1T[r][u] = fc1w[u][r]   (8192 elements)
// ---------------------------------------------------------------------------
__global__ void transpose_fc1_kernel(const float* __restrict__ fc1w) {
    int i = blockIdx.x * 256 + threadIdx.x;     // 0..8191
    int u = i >> 7, r = i & 127;
    W1T[r * 64 + u] = fc1w[i];
}

// ---------------------------------------------------------------------------
// Fused diffusion along diagonal chains (f32x2-packed over the feature dim).
// Chain (b,s): z_0 = x[b,s]; for k=1..K:  z_k = z_{k-1} @ S[b, s+k],
// written to Zbuf[k] at t = s+k, layout [n][f] (8 floats per node).
// CTA = one chain. 160 threads: warps 0-3 compute (lanes 0..99 = column m),
// warp 4 = cp.async loader double-buffering the 40KB S matrix.
// ---------------------------------------------------------------------------
__global__ void __launch_bounds__(160) diff_chain_kernel(const float* __restrict__ x,
                                                         const float* __restrict__ S) {
    extern __shared__ float dsm[];
    float* Sb0 = dsm;                 // S buffers: 2 x 10000 floats
    float* Sb1 = dsm + 10000;
    float* zb0 = dsm + 20000;         // z buffers: 2 x 800 floats, layout [n][f]
    float* zb1 = dsm + 20000 + 800;

    int blk = blockIdx.x;
    int b = blk >> 6, s = blk & 63;
    int K = (NEXD < (63 - s)) ? NEXD : (63 - s);
    if (K <= 0) return;               // s = 63: no work (all threads exit together)
    int tid = threadIdx.x;

    const float* Sg = S + (size_t)(b * TT + s) * (NN * NN);   // S[b][s+k] = Sg + k*10000

    if (tid >= 128) {
        // loader prologue: S_1 -> Sb1
        int lane = tid - 128;
        const float4* src = reinterpret_cast<const float4*>(Sg + NN * NN);
        unsigned dst = (unsigned)__cvta_generic_to_shared(Sb1);
        for (int i = lane; i < 2500; i += 32)
            asm volatile("cp.async.cg.shared.global [%0], [%1], 16;"
                         :: "r"(dst + i * 16), "l"(src + i));
        asm volatile("cp.async.commit_group;");
    } else {
        // z_0 = x[b][s] (input layout [f][n]) -> zb0 [n][f]
        const float* xr = x + (size_t)(b * TT + s) * (F0D * NN);
        for (int i = tid; i < F0D * NN; i += 128) {
            int n = i >> 3, f = i & 7;
            zb0[i] = xr[f * NN + n];
        }
    }

    float* zp = zb0;
    float* zc = zb1;
    for (int k = 1; k <= K; k++) {
        __syncthreads();              // (A) compute k-1 done -> S buffer being refilled is free
        if (tid >= 128) {
            if (k < K) {
                int lane = tid - 128;
                const float4* src = reinterpret_cast<const float4*>(Sg + (size_t)(k + 1) * (NN * NN));
                unsigned dst = (unsigned)__cvta_generic_to_shared(((k + 1) & 1) ? Sb1 : Sb0);
                for (int i = lane; i < 2500; i += 32)
                    asm volatile("cp.async.cg.shared.global [%0], [%1], 16;"
                                 :: "r"(dst + i * 16), "l"(src + i));
                asm volatile("cp.async.commit_group;");
                asm volatile("cp.async.wait_group 1;");   // S_k complete, S_{k+1} in flight
            } else {
                asm volatile("cp.async.wait_group 0;");   // S_K complete
            }
        }
        __syncthreads();              // (B) S_k visible to compute warps
        if (tid < NN) {
            const float* Ss = (k & 1) ? Sb1 : Sb0;
            unsigned long long a0 = 0ull, a1 = 0ull, a2 = 0ull, a3 = 0ull; // = (0.f,0.f)
#pragma unroll 4
            for (int n = 0; n < NN; n++) {
                float sv = Ss[n * NN + tid];                      // conflict-free LDS
                unsigned long long s2 = bcast2(sv);
                const ulonglong2* zr2 = reinterpret_cast<const ulonglong2*>(zp + n * 8);
                ulonglong2 za = zr2[0];                           // broadcast LDS.128
                ulonglong2 zb_ = zr2[1];
                FMA2(a0, za.x, s2);
                FMA2(a1, za.y, s2);
                FMA2(a2, zb_.x, s2);
                FMA2(a3, zb_.y, s2);
            }
            // store packed results (bit-exact float pairs) to SMEM + global
            ulonglong2* zdst = reinterpret_cast<ulonglong2*>(zc + tid * 8);
            zdst[0] = make_ulonglong2(a0, a1);
            zdst[1] = make_ulonglong2(a2, a3);
            float* outp = Zbuf + (size_t)k * PLANE + (size_t)(b * TT + s + k) * (F0D * NN);
            ulonglong2* gdst = reinterpret_cast<ulonglong2*>(outp + tid * 8);
            gdst[0] = make_ulonglong2(a0, a1);
            gdst[1] = make_ulonglong2(a2, a3);
        }
        float* tmp = zp; zp = zc; zc = tmp;
    }
}

// ---------------------------------------------------------------------------
// conv1 (K=4) + relu + maxpool2 : z[8][16] -> Q1[32][6]   (thread = node g)
// k=0 plane read straight from x ([f][n] layout); k>=1 from Zbuf [n][f] layout
// (2 contiguous float4 per k). Planes with k > t are implicit zeros.
// ---------------------------------------------------------------------------
__global__ void __launch_bounds__(256) conv1_kernel(const float* __restrict__ x,
                                                    const float* __restrict__ w1,
                                                    const float* __restrict__ b1) {
    __shared__ __align__(16) float w1s[F1C * F0D * 4];
    __shared__ float b1s[F1C];
    int tid = threadIdx.x;
    for (int i = tid; i < F1C * F0D * 4; i += 256) w1s[i] = w1[i];
    if (tid < F1C) b1s[tid] = b1[tid];
    __syncthreads();

    int g = blockIdx.x * 256 + tid;
    int bt = g / NN, n = g - bt * NN;
    int t = bt & (TT - 1);
    const float* zb = Zbuf + (size_t)bt * (F0D * NN) + n * 8;   // + k*PLANE per k
    const float* xb = x + (size_t)bt * (F0D * NN) + n;

    float zr[F0D * LD];
#pragma unroll
    for (int f = 0; f < F0D; f++)
        zr[f * LD + 0] = xb[f * NN];
#pragma unroll
    for (int k = 1; k < LD; k++) {
        if (k <= t) {
            float4 p0 = *reinterpret_cast<const float4*>(zb + (size_t)k * PLANE);
            float4 p1 = *reinterpret_cast<const float4*>(zb + (size_t)k * PLANE + 4);
            zr[0 * LD + k] = p0.x; zr[1 * LD + k] = p0.y;
            zr[2 * LD + k] = p0.z; zr[3 * LD + k] = p0.w;
            zr[4 * LD + k] = p1.x; zr[5 * LD + k] = p1.y;
            zr[6 * LD + k] = p1.z; zr[7 * LD + k] = p1.w;
        } else {
#pragma unroll
            for (int f = 0; f < F0D; f++) zr[f * LD + k] = 0.f;
        }
    }

#pragma unroll
    for (int i = 0; i < 6; i++) {
        for (int c = 0; c < F1C; c++) {
            float a0 = b1s[c], a1 = a0;
            const float4* wc = reinterpret_cast<const float4*>(&w1s[c * 32]);
#pragma unroll
            for (int f = 0; f < F0D; f++) {
                float4 w = wc[f];
                a0 = fmaf(zr[f * LD + 2 * i + 0], w.x, a0);
                a1 = fmaf(zr[f * LD + 2 * i + 1], w.x, a1);
                a0 = fmaf(zr[f * LD + 2 * i + 1], w.y, a0);
                a1 = fmaf(zr[f * LD + 2 * i + 2], w.y, a1);
                a0 = fmaf(zr[f * LD + 2 * i + 2], w.z, a0);
                a1 = fmaf(zr[f * LD + 2 * i + 3], w.z, a1);
                a0 = fmaf(zr[f * LD + 2 * i + 3], w.w, a0);
                a1 = fmaf(zr[f * LD + 2 * i + 4], w.w, a1);
            }
            Q1buf[(c * 6 + i) * MTOT + g] = fmaxf(fmaxf(a0, a1), 0.f);
        }
    }
}

// ---------------------------------------------------------------------------
// conv2 (K=3) + relu + maxpool2 : Q1[32][6] -> Q2[64][2]  (thread = node g)
// ---------------------------------------------------------------------------
__global__ void __launch_bounds__(256) conv2_kernel(const float* __restrict__ w2,
                                                    const float* __restrict__ b2) {
    __shared__ __align__(16) float w2s[F2C * F1C * 3];
    __shared__ float b2s[F2C];
    int tid = threadIdx.x;
    for (int i = tid; i < F2C * F1C * 3; i += 256) w2s[i] = w2[i];
    if (tid < F2C) b2s[tid] = b2[tid];
    __syncthreads();

    int g = blockIdx.x * 256 + tid;

#pragma unroll
    for (int i = 0; i < 2; i++) {
        float qw[F1C * 4];
#pragma unroll
        for (int c = 0; c < F1C; c++)
#pragma unroll
            for (int col = 0; col < 4; col++)
                qw[c * 4 + col] = Q1buf[(c * 6 + 2 * i + col) * MTOT + g];

        for (int d = 0; d < F2C; d++) {
            float a0 = b2s[d], a1 = a0;
            const float4* wd = reinterpret_cast<const float4*>(&w2s[d * 96]);
#pragma unroll
            for (int cc = 0; cc < 24; cc++) {
                float4 w = wd[cc];
                int l = cc * 4;
                { int c = (l + 0) / 3, j = (l + 0) % 3;
                  a0 = fmaf(qw[c * 4 + j], w.x, a0); a1 = fmaf(qw[c * 4 + j + 1], w.x, a1); }
                { int c = (l + 1) / 3, j = (l + 1) % 3;
                  a0 = fmaf(qw[c * 4 + j], w.y, a0); a1 = fmaf(qw[c * 4 + j + 1], w.y, a1); }
                { int c = (l + 2) / 3, j = (l + 2) % 3;
                  a0 = fmaf(qw[c * 4 + j], w.z, a0); a1 = fmaf(qw[c * 4 + j + 1], w.z, a1); }
                { int c = (l + 3) / 3, j = (l + 3) % 3;
                  a0 = fmaf(qw[c * 4 + j], w.w, a0); a1 = fmaf(qw[c * 4 + j + 1], w.w, a1); }
            }
            Q2buf[(d * 2 + i) * MTOT + g] = fmaxf(fmaxf(a0, a1), 0.f);
        }
    }
}

// ---------------------------------------------------------------------------
// fc1 + relu + fc2 : Q2[128] -> out[5]   (thread = node g), out [b][t][o][n]
// Streaming form: 32 packed hidden-unit-pair accumulators; q streamed scalar;
// weights from W1T ([r][u], pre-transposed) staged in SMEM.
// ---------------------------------------------------------------------------
__global__ void __launch_bounds__(256, 2) fc_kernel(const float* __restrict__ fc1b,
                                                    const float* __restrict__ fc2w,
                                                    const float* __restrict__ fc2b,
                                                    float* __restrict__ out) {
    __shared__ __align__(16) float w1t[128 * 64];   // [r][u]
    __shared__ __align__(8) float b1s[64];
    __shared__ float w2s[5 * 64];
    __shared__ float b2s[5];
    int tid = threadIdx.x;
    for (int i = tid; i < 128 * 64; i += 256) w1t[i] = W1T[i];   // coalesced, conflict-free
    if (tid < 64) b1s[tid] = fc1b[tid];
    for (int i = tid; i < 5 * 64; i += 256) w2s[i] = fc2w[i];
    if (tid < 5) b2s[tid] = fc2b[tid];
    __syncthreads();

    int g = blockIdx.x * 256 + tid;

    unsigned long long h2[32];                       // pairs (h[2j], h[2j+1]), init = bias
#pragma unroll
    for (int j = 0; j < 32; j++)
        h2[j] = *reinterpret_cast<const unsigned long long*>(&b1s[2 * j]);

    const float* qp = Q2buf + g;
#pragma unroll 4
    for (int r = 0; r < 128; r++) {
        float qr = qp[(size_t)r * MTOT];             // coalesced LDG
        unsigned long long q2 = bcast2(qr);
        const ulonglong2* wr = reinterpret_cast<const ulonglong2*>(&w1t[r * 64]);
#pragma unroll
        for (int j4 = 0; j4 < 16; j4++) {            // 16 x LDS.128 broadcast = 32 pairs
            ulonglong2 wp = wr[j4];
            FMA2(h2[2 * j4 + 0], wp.x, q2);
            FMA2(h2[2 * j4 + 1], wp.y, q2);
        }
    }

    float o[5];
#pragma unroll
    for (int oo = 0; oo < 5; oo++) o[oo] = b2s[oo];

#pragma unroll
    for (int j = 0; j < 32; j++) {
        float hlo, hhi;
        asm("mov.b64 {%0, %1}, %2;" : "=r"(*(unsigned*)&hlo), "=r"(*(unsigned*)&hhi) : "l"(h2[j]));
        hlo = fmaxf(hlo, 0.f);
        hhi = fmaxf(hhi, 0.f);
#pragma unroll
        for (int oo = 0; oo < 5; oo++) {
            o[oo] = fmaf(hlo, w2s[oo * 64 + 2 * j + 0], o[oo]);
            o[oo] = fmaf(hhi, w2s[oo * 64 + 2 * j + 1], o[oo]);
        }
    }

    int bt = g / NN, n = g - bt * NN;
#pragma unroll
    for (int oo = 0; oo < 5; oo++)
        out[(size_t)(bt * 5 + oo) * NN + n] = o[oo];
}

// ---------------------------------------------------------------------------
// Launch: fc1-weight transpose; fused diffusion; conv1; conv2; fc.
// ---------------------------------------------------------------------------
extern "C" void kernel_launch(void* const* d_in, const int* in_sizes, int n_in,
                              void* d_out, int out_size) {
    const float* x      = (const float*)d_in[0];
    const float* S      = (const float*)d_in[1];
    const float* conv1w = (const float*)d_in[2];
    const float* conv1b = (const float*)d_in[3];
    const float* conv2w = (const float*)d_in[4];
    const float* conv2b = (const float*)d_in[5];
    const float* fc1w   = (const float*)d_in[6];
    const float* fc1b   = (const float*)d_in[7];
    const float* fc2w   = (const float*)d_in[8];
    const float* fc2b   = (const float*)d_in[9];
    float* out = (float*)d_out;

    const int dsm_bytes = (2 * NN * NN + 2 * F0D * NN) * (int)sizeof(float);  // 86400
    cudaFuncSetAttribute(diff_chain_kernel,
                         cudaFuncAttributeMaxDynamicSharedMemorySize, dsm_bytes);

    transpose_fc1_kernel<<<32, 256>>>(fc1w);
    diff_chain_kernel<<<BT, 160, dsm_bytes>>>(x, S);
    conv1_kernel<<<MTOT / 256, 256>>>(x, conv1w, conv1b);
    conv2_kernel<<<MTOT / 256, 256>>>(conv2w, conv2b);
    fc_kernel<<<MTOT / 256, 256>>>(fc1b, fc2w, fc2b, out);
}